// round 3
// baseline (speedup 1.0000x reference)
#include <cuda_runtime.h>
#include <math.h>
#include <stdint.h>

#define NN 50000
#define EE 800000
#define ETOT (EE + NN)

// ---------------- device scratch (no allocations allowed) ----------------
__device__ __align__(16) float    g_h[NN * 64];     // pre-attention features
__device__ __align__(16) float    g_out[NN * 64];   // numerator accumulators
__device__ __align__(16) float    g_feat[NN * 64];  // layer output -> next input
__device__ __align__(16) float    g_as[NN * 4];     // alpha_src per (node, head)
__device__ __align__(16) float    g_ad[NN * 4];     // alpha_dst per (node, head)
__device__ __align__(16) unsigned g_emax[NN * 4];   // encoded float max per (node, head)
__device__ __align__(16) float    g_denom[NN * 4];  // softmax denominators

// monotone float<->uint encoding for atomicMax on signed floats
__device__ __forceinline__ unsigned enc_f(float f) {
    unsigned b = __float_as_uint(f);
    return (b & 0x80000000u) ? ~b : (b | 0x80000000u);
}
__device__ __forceinline__ float dec_f(unsigned u) {
    unsigned b = (u & 0x80000000u) ? (u & 0x7FFFFFFFu) : ~u;
    return __uint_as_float(b);
}

__device__ __forceinline__ void red_add_v4(float* p, float a, float b, float c, float d) {
    asm volatile("red.global.add.v4.f32 [%0], {%1,%2,%3,%4};"
                 :: "l"(p), "f"(a), "f"(b), "f"(c), "f"(d) : "memory");
}

// ---------------- GEMM: C[n, FOUT] = X[n, FIN] * W[FIN, FOUT] ----------------
template <int FIN, int FOUT, int TK>
__global__ void gemm_kernel(const float* __restrict__ X, const float* __restrict__ W,
                            float* __restrict__ C, int nrows) {
    constexpr int CG = FOUT / 4;
    constexpr int TM = 128;
    constexpr int XPITCH = TK + 4;
    extern __shared__ float smem[];
    float* Xs = smem;                   // TM * XPITCH
    float* Ws = smem + TM * XPITCH;     // TK * FOUT

    const int tid = threadIdx.x;
    const int cg = tid % CG;
    const int rg = tid / CG;            // 0..15
    const int rowBase = blockIdx.x * TM;

    float acc[8][4];
#pragma unroll
    for (int i = 0; i < 8; i++)
#pragma unroll
        for (int j = 0; j < 4; j++) acc[i][j] = 0.f;

    for (int k0 = 0; k0 < FIN; k0 += TK) {
        __syncthreads();
        for (int idx = tid; idx < TM * (TK / 4); idx += blockDim.x) {
            int r = idx / (TK / 4);
            int k4 = idx % (TK / 4);
            float4 v = make_float4(0.f, 0.f, 0.f, 0.f);
            int row = rowBase + r;
            if (row < nrows)
                v = *(const float4*)(X + (size_t)row * FIN + k0 + k4 * 4);
            *(float4*)(Xs + r * XPITCH + k4 * 4) = v;
        }
        for (int idx = tid; idx < TK * CG; idx += blockDim.x) {
            int k = idx / CG;
            int c4 = idx % CG;
            *(float4*)(Ws + k * FOUT + c4 * 4) =
                *(const float4*)(W + (size_t)(k0 + k) * FOUT + c4 * 4);
        }
        __syncthreads();

#pragma unroll 4
        for (int k = 0; k < TK; k++) {
            float4 w = *(float4*)(Ws + k * FOUT + cg * 4);
#pragma unroll
            for (int i = 0; i < 8; i++) {
                float xv = Xs[(rg * 8 + i) * XPITCH + k];
                acc[i][0] += xv * w.x;
                acc[i][1] += xv * w.y;
                acc[i][2] += xv * w.z;
                acc[i][3] += xv * w.w;
            }
        }
    }

#pragma unroll
    for (int i = 0; i < 8; i++) {
        int row = rowBase + rg * 8 + i;
        if (row < nrows) {
            float4 v = make_float4(acc[i][0], acc[i][1], acc[i][2], acc[i][3]);
            *(float4*)(C + (size_t)row * FOUT + cg * 4) = v;
        }
    }
}

// ---------------- per-node attention logits ----------------
template <int H, int C>
__global__ void alpha_kernel(const float* __restrict__ h,
                             const float* __restrict__ a_src,
                             const float* __restrict__ a_dst) {
    int t = blockIdx.x * blockDim.x + threadIdx.x;
    if (t >= NN * H) return;
    int n = t / H, hh = t % H;
    const float* hp = h + (size_t)n * (H * C) + hh * C;
    const float* sv = a_src + hh * C;
    const float* dv = a_dst + hh * C;
    float s1 = 0.f, s2 = 0.f;
#pragma unroll
    for (int c = 0; c < C; c++) {
        float v = hp[c];
        s1 += v * sv[c];
        s2 += v * dv[c];
    }
    g_as[t] = s1;
    g_ad[t] = s2;
}

// ---------------- zero accumulators ----------------
__global__ void zero_kernel() {
    int i = blockIdx.x * blockDim.x + threadIdx.x;
    if (i < NN * 64) g_out[i] = 0.f;
    if (i < NN * 4) {
        g_denom[i] = 0.f;
        g_emax[i] = 0u;
    }
}

// ---------------- edge pass 1: segment max ----------------
template <int H>
__global__ void edge_max_kernel(const int* __restrict__ srcs,
                                const int* __restrict__ dsts) {
    int e = blockIdx.x * blockDim.x + threadIdx.x;
    if (e >= ETOT) return;
    int s, d;
    if (e < EE) { s = srcs[e]; d = dsts[e]; }
    else        { s = d = e - EE; }
#pragma unroll
    for (int hh = 0; hh < H; hh++) {
        float v = g_as[s * H + hh] + g_ad[d * H + hh];
        v = v > 0.f ? v : 0.2f * v;
        atomicMax(&g_emax[d * H + hh], enc_f(v));
    }
}

// ---------------- edge pass 2: exp + scatter numerator & denominator ----------------
template <int H, int C>
__global__ void edge_scatter_kernel(const int* __restrict__ srcs,
                                    const int* __restrict__ dsts,
                                    const float* __restrict__ h) {
    int e = blockIdx.x * blockDim.x + threadIdx.x;
    if (e >= ETOT) return;
    int s, d;
    if (e < EE) { s = srcs[e]; d = dsts[e]; }
    else        { s = d = e - EE; }

    float w[H];
#pragma unroll
    for (int hh = 0; hh < H; hh++) {
        float v = g_as[s * H + hh] + g_ad[d * H + hh];
        v = v > 0.f ? v : 0.2f * v;
        w[hh] = expf(v - dec_f(g_emax[d * H + hh]));
    }
    if (H == 4) {
        red_add_v4(g_denom + d * 4, w[0], w[1], w[2], w[3 % H]);
    } else {
        atomicAdd(g_denom + d, w[0]);
    }

    const float4* hp = (const float4*)(h + (size_t)s * (H * C));
    float* op = g_out + (size_t)d * (H * C);
#pragma unroll
    for (int q = 0; q < (H * C) / 4; q++) {
        float4 v = __ldg(hp + q);
        float ww = w[(q * 4) / C];
        red_add_v4(op + q * 4, v.x * ww, v.y * ww, v.z * ww, v.w * ww);
    }
}

// ---------------- finalize: divide, bias, optional relu ----------------
template <int H, int C, bool RELU>
__global__ void finalize_kernel(const float* __restrict__ bias, float* __restrict__ dest) {
    int t = blockIdx.x * blockDim.x + threadIdx.x;
    if (t >= NN * H * C) return;
    int n = t / (H * C);
    int j = t % (H * C);
    float v = g_out[t] / (g_denom[n * H + j / C] + 1e-16f) + bias[j];
    if (RELU) v = v > 0.f ? v : 0.f;
    dest[t] = v;
}

// ---------------- launch ----------------
extern "C" void kernel_launch(void* const* d_in, const int* in_sizes, int n_in,
                              void* d_out, int out_size) {
    const float* x = (const float*)d_in[0];
    const int* ei = (const int*)d_in[1];    // int32! (JAX x64 disabled)
    const float* W1 = (const float*)d_in[2];
    const float* asr1 = (const float*)d_in[3];
    const float* adr1 = (const float*)d_in[4];
    const float* b1 = (const float*)d_in[5];
    const float* W2 = (const float*)d_in[6];
    const float* asr2 = (const float*)d_in[7];
    const float* adr2 = (const float*)d_in[8];
    const float* b2 = (const float*)d_in[9];
    const float* W3 = (const float*)d_in[10];
    const float* asr3 = (const float*)d_in[11];
    const float* adr3 = (const float*)d_in[12];
    const float* b3 = (const float*)d_in[13];
    float* out = (float*)d_out;

    const int* esrc = ei;
    const int* edst = ei + EE;

    float *p_h, *p_feat;
    cudaGetSymbolAddress((void**)&p_h, g_h);
    cudaGetSymbolAddress((void**)&p_feat, g_feat);

    constexpr int SMEM1 = (128 * (64 + 4) + 64 * 64) * 4;  // 51200
    constexpr int SMEM3 = (128 * (64 + 4) + 64 * 40) * 4;  // 45056
    cudaFuncSetAttribute((const void*)gemm_kernel<256, 64, 64>,
                         cudaFuncAttributeMaxDynamicSharedMemorySize, SMEM1);
    cudaFuncSetAttribute((const void*)gemm_kernel<64, 64, 64>,
                         cudaFuncAttributeMaxDynamicSharedMemorySize, SMEM1);
    cudaFuncSetAttribute((const void*)gemm_kernel<64, 40, 64>,
                         cudaFuncAttributeMaxDynamicSharedMemorySize, SMEM3);

    const int gemmGrid = (NN + 127) / 128;
    const int zeroGrid = (NN * 64 + 255) / 256;
    const int edgeGrid = (ETOT + 255) / 256;

    // ---------------- layer 1: 256 -> 4x16 ----------------
    gemm_kernel<256, 64, 64><<<gemmGrid, 256, SMEM1>>>(x, W1, p_h, NN);
    zero_kernel<<<zeroGrid, 256>>>();
    alpha_kernel<4, 16><<<(NN * 4 + 127) / 128, 128>>>(p_h, asr1, adr1);
    edge_max_kernel<4><<<edgeGrid, 256>>>(esrc, edst);
    edge_scatter_kernel<4, 16><<<edgeGrid, 256>>>(esrc, edst, p_h);
    finalize_kernel<4, 16, true><<<(NN * 64 + 255) / 256, 256>>>(b1, p_feat);

    // ---------------- layer 2: 64 -> 4x16 ----------------
    gemm_kernel<64, 64, 64><<<gemmGrid, 256, SMEM1>>>(p_feat, W2, p_h, NN);
    zero_kernel<<<zeroGrid, 256>>>();
    alpha_kernel<4, 16><<<(NN * 4 + 127) / 128, 128>>>(p_h, asr2, adr2);
    edge_max_kernel<4><<<edgeGrid, 256>>>(esrc, edst);
    edge_scatter_kernel<4, 16><<<edgeGrid, 256>>>(esrc, edst, p_h);
    finalize_kernel<4, 16, true><<<(NN * 64 + 255) / 256, 256>>>(b2, p_feat);

    // ---------------- layer 3: 64 -> 1x40 ----------------
    gemm_kernel<64, 40, 64><<<gemmGrid, 160, SMEM3>>>(p_feat, W3, p_h, NN);
    zero_kernel<<<zeroGrid, 256>>>();
    alpha_kernel<1, 40><<<(NN + 127) / 128, 128>>>(p_h, asr3, adr3);
    edge_max_kernel<1><<<edgeGrid, 256>>>(esrc, edst);
    edge_scatter_kernel<1, 40><<<edgeGrid, 256>>>(esrc, edst, p_h);
    finalize_kernel<1, 40, false><<<(NN * 40 + 255) / 256, 256>>>(b3, out);
}

// round 4
// speedup vs baseline: 1.6799x; 1.6799x over previous
#include <cuda_runtime.h>
#include <math.h>
#include <stdint.h>

#define NN 50000
#define EE 800000
#define ETOT (EE + NN)

// ---------------- device scratch ----------------
__device__ __align__(16) float g_h[NN * 64];     // pre-attention features
__device__ __align__(16) float g_out[NN * 64];   // numerator accumulators
__device__ __align__(16) float g_feat[NN * 64];  // layer output -> next input
__device__ __align__(16) float g_as[NN * 4];     // alpha_src per (node, head)
__device__ __align__(16) float g_ad[NN * 4];     // alpha_dst per (node, head)
__device__ __align__(16) float g_denom[NN * 4];  // softmax denominators

__device__ __forceinline__ void red_add_v4(float* p, float a, float b, float c, float d) {
    asm volatile("red.global.add.v4.f32 [%0], {%1,%2,%3,%4};"
                 :: "l"(p), "f"(a), "f"(b), "f"(c), "f"(d) : "memory");
}

// ---------------- GEMM: C[n, FOUT] = X[n, FIN] * W[FIN, FOUT] ----------------
template <int FIN, int FOUT, int TK>
__global__ void gemm_kernel(const float* __restrict__ X, const float* __restrict__ W,
                            float* __restrict__ C, int nrows) {
    constexpr int CG = FOUT / 4;
    constexpr int TM = 128;
    constexpr int XPITCH = TK + 4;
    extern __shared__ float smem[];
    float* Xs = smem;                   // TM * XPITCH
    float* Ws = smem + TM * XPITCH;     // TK * FOUT

    const int tid = threadIdx.x;
    const int cg = tid % CG;
    const int rg = tid / CG;
    const int rowBase = blockIdx.x * TM;

    float acc[8][4];
#pragma unroll
    for (int i = 0; i < 8; i++)
#pragma unroll
        for (int j = 0; j < 4; j++) acc[i][j] = 0.f;

    for (int k0 = 0; k0 < FIN; k0 += TK) {
        __syncthreads();
        for (int idx = tid; idx < TM * (TK / 4); idx += blockDim.x) {
            int r = idx / (TK / 4);
            int k4 = idx % (TK / 4);
            float4 v = make_float4(0.f, 0.f, 0.f, 0.f);
            int row = rowBase + r;
            if (row < nrows)
                v = *(const float4*)(X + (size_t)row * FIN + k0 + k4 * 4);
            *(float4*)(Xs + r * XPITCH + k4 * 4) = v;
        }
        for (int idx = tid; idx < TK * CG; idx += blockDim.x) {
            int k = idx / CG;
            int c4 = idx % CG;
            *(float4*)(Ws + k * FOUT + c4 * 4) =
                *(const float4*)(W + (size_t)(k0 + k) * FOUT + c4 * 4);
        }
        __syncthreads();

#pragma unroll 4
        for (int k = 0; k < TK; k++) {
            float4 w = *(float4*)(Ws + k * FOUT + cg * 4);
#pragma unroll
            for (int i = 0; i < 8; i++) {
                float xv = Xs[(rg * 8 + i) * XPITCH + k];
                acc[i][0] += xv * w.x;
                acc[i][1] += xv * w.y;
                acc[i][2] += xv * w.z;
                acc[i][3] += xv * w.w;
            }
        }
    }

#pragma unroll
    for (int i = 0; i < 8; i++) {
        int row = rowBase + rg * 8 + i;
        if (row < nrows) {
            float4 v = make_float4(acc[i][0], acc[i][1], acc[i][2], acc[i][3]);
            *(float4*)(C + (size_t)row * FOUT + cg * 4) = v;
        }
    }
}

// ---------------- prep: attention logits + zero accumulators (fused) ----------------
// thread per (node, head): computes alpha_src/alpha_dst, zeroes denom + its C-slice of g_out
template <int H, int C>
__global__ void prep_kernel(const float* __restrict__ h,
                            const float* __restrict__ a_src,
                            const float* __restrict__ a_dst) {
    int t = blockIdx.x * blockDim.x + threadIdx.x;
    if (t >= NN * H) return;
    int n = t / H, hh = t % H;
    const float* hp = h + (size_t)n * (H * C) + hh * C;
    const float* sv = a_src + hh * C;
    const float* dv = a_dst + hh * C;
    float s1 = 0.f, s2 = 0.f;
#pragma unroll
    for (int c = 0; c < C; c++) {
        float v = hp[c];
        s1 += v * sv[c];
        s2 += v * dv[c];
    }
    g_as[t] = s1;
    g_ad[t] = s2;
    g_denom[t] = 0.f;
    float4 z = make_float4(0.f, 0.f, 0.f, 0.f);
    float* op = g_out + (size_t)n * (H * C) + hh * C;
#pragma unroll
    for (int q = 0; q < C / 4; q++) *(float4*)(op + q * 4) = z;
}

// ---------------- edge scatter: 16 lanes per edge, no max pass ----------------
// Softmax is shift-invariant; logits are glorot-scale-bounded so raw exp is safe.
template <int H, int C>
__global__ void edge_scatter_kernel(const int* __restrict__ srcs,
                                    const int* __restrict__ dsts,
                                    const float* __restrict__ h) {
    constexpr int F = H * C;       // 64 or 40
    constexpr int NV = F / 4;      // float4 count: 16 or 10
    int gt = blockIdx.x * blockDim.x + threadIdx.x;
    int e = gt >> 4;
    int q = gt & 15;
    if (e >= ETOT) return;
    int s, d;
    if (e < EE) { s = __ldg(srcs + e); d = __ldg(dsts + e); }
    else        { s = d = e - EE; }

    // this lane's head and softmax weight
    int hh = (H == 1) ? 0 : (q * C / 64);   // H=4,C=16: q/4 ; H=1: 0
    float v = g_as[s * H + hh] + g_ad[d * H + hh];
    v = v > 0.f ? v : 0.2f * v;
    float w = __expf(v);

    if (H == 4) {
        // lane q==0 of each 16-lane group emits the 4-head denominator
        int base = (threadIdx.x & 16);  // group offset within warp
        float w0 = __shfl_sync(0xffffffffu, w, base + 0);
        float w1 = __shfl_sync(0xffffffffu, w, base + 4);
        float w2 = __shfl_sync(0xffffffffu, w, base + 8);
        float w3 = __shfl_sync(0xffffffffu, w, base + 12);
        if (q == 0) red_add_v4(g_denom + d * 4, w0, w1, w2, w3);
    } else {
        if (q == 0) atomicAdd(g_denom + d, w);
    }

    if (q < NV) {
        float4 x = __ldg((const float4*)(h + (size_t)s * F) + q);
        red_add_v4(g_out + (size_t)d * F + q * 4, x.x * w, x.y * w, x.z * w, x.w * w);
    }
}

// ---------------- finalize: divide, bias, optional relu ----------------
template <int H, int C, bool RELU>
__global__ void finalize_kernel(const float* __restrict__ bias, float* __restrict__ dest) {
    int t = blockIdx.x * blockDim.x + threadIdx.x;
    if (t >= NN * H * C) return;
    int n = t / (H * C);
    int j = t % (H * C);
    float v = g_out[t] / (g_denom[n * H + j / C] + 1e-16f) + bias[j];
    if (RELU) v = v > 0.f ? v : 0.f;
    dest[t] = v;
}

// ---------------- launch ----------------
extern "C" void kernel_launch(void* const* d_in, const int* in_sizes, int n_in,
                              void* d_out, int out_size) {
    const float* x = (const float*)d_in[0];
    const int* ei = (const int*)d_in[1];    // int32 (JAX x64 disabled)
    const float* W1 = (const float*)d_in[2];
    const float* asr1 = (const float*)d_in[3];
    const float* adr1 = (const float*)d_in[4];
    const float* b1 = (const float*)d_in[5];
    const float* W2 = (const float*)d_in[6];
    const float* asr2 = (const float*)d_in[7];
    const float* adr2 = (const float*)d_in[8];
    const float* b2 = (const float*)d_in[9];
    const float* W3 = (const float*)d_in[10];
    const float* asr3 = (const float*)d_in[11];
    const float* adr3 = (const float*)d_in[12];
    const float* b3 = (const float*)d_in[13];
    float* out = (float*)d_out;

    const int* esrc = ei;
    const int* edst = ei + EE;

    float *p_h, *p_feat;
    cudaGetSymbolAddress((void**)&p_h, g_h);
    cudaGetSymbolAddress((void**)&p_feat, g_feat);

    constexpr int SMEM1 = (128 * (64 + 4) + 64 * 64) * 4;
    constexpr int SMEM3 = (128 * (64 + 4) + 64 * 40) * 4;
    cudaFuncSetAttribute((const void*)gemm_kernel<256, 64, 64>,
                         cudaFuncAttributeMaxDynamicSharedMemorySize, SMEM1);
    cudaFuncSetAttribute((const void*)gemm_kernel<64, 64, 64>,
                         cudaFuncAttributeMaxDynamicSharedMemorySize, SMEM1);
    cudaFuncSetAttribute((const void*)gemm_kernel<64, 40, 64>,
                         cudaFuncAttributeMaxDynamicSharedMemorySize, SMEM3);

    const int gemmGrid = (NN + 127) / 128;
    const int scatGrid = (ETOT * 16 + 255) / 256;

    // ---------------- layer 1: 256 -> 4x16 ----------------
    gemm_kernel<256, 64, 64><<<gemmGrid, 256, SMEM1>>>(x, W1, p_h, NN);
    prep_kernel<4, 16><<<(NN * 4 + 255) / 256, 256>>>(p_h, asr1, adr1);
    edge_scatter_kernel<4, 16><<<scatGrid, 256>>>(esrc, edst, p_h);
    finalize_kernel<4, 16, true><<<(NN * 64 + 255) / 256, 256>>>(b1, p_feat);

    // ---------------- layer 2: 64 -> 4x16 ----------------
    gemm_kernel<64, 64, 64><<<gemmGrid, 256, SMEM1>>>(p_feat, W2, p_h, NN);
    prep_kernel<4, 16><<<(NN * 4 + 255) / 256, 256>>>(p_h, asr2, adr2);
    edge_scatter_kernel<4, 16><<<scatGrid, 256>>>(esrc, edst, p_h);
    finalize_kernel<4, 16, true><<<(NN * 64 + 255) / 256, 256>>>(b2, p_feat);

    // ---------------- layer 3: 64 -> 1x40 ----------------
    gemm_kernel<64, 40, 64><<<gemmGrid, 160, SMEM3>>>(p_feat, W3, p_h, NN);
    prep_kernel<1, 40><<<(NN + 255) / 256, 256>>>(p_h, asr3, adr3);
    edge_scatter_kernel<1, 40><<<scatGrid, 256>>>(esrc, edst, p_h);
    finalize_kernel<1, 40, false><<<(NN * 40 + 255) / 256, 256>>>(b3, out);
}

// round 5
// speedup vs baseline: 2.0054x; 1.1938x over previous
#include <cuda_runtime.h>
#include <math.h>
#include <stdint.h>

#define NN 50000
#define EE 800000
#define ETOT (EE + NN)

// ---------------- device scratch ----------------
__device__ __align__(16) float g_h[NN * 64];     // pre-attention features
__device__ __align__(16) float g_feat[NN * 64];  // layer output -> next input
__device__ __align__(16) float g_as[NN * 4];     // alpha_src per (node, head)
__device__ __align__(16) float g_ad[NN * 4];     // alpha_dst per (node, head)
__device__ int g_deg[NN];         // in-degree histogram
__device__ int g_rowptr[NN + 1];  // CSR row pointers
__device__ int g_cursor[NN];      // fill cursors
__device__ int g_csr[ETOT];       // CSR src indices (incl. self loops)

// ---------------- packed f32x2 helpers ----------------
__device__ __forceinline__ void ffma2(unsigned long long& acc, unsigned long long a,
                                      unsigned long long b) {
    asm("fma.rn.f32x2 %0, %1, %2, %0;" : "+l"(acc) : "l"(a), "l"(b));
}
__device__ __forceinline__ unsigned long long bcast2(float x) {
    unsigned long long r;
    asm("mov.b64 %0, {%1, %1};" : "=l"(r) : "f"(x));
    return r;
}
__device__ __forceinline__ float2 unpack2(unsigned long long p) {
    float2 f;
    asm("mov.b64 {%0, %1}, %2;" : "=f"(f.x), "=f"(f.y) : "l"(p));
    return f;
}

// ---------------- GEMM: C[n, FOUT] = X[n, FIN] * W[FIN, FOUT] (f32x2 FMA) ----------------
template <int FIN, int FOUT, int TK>
__global__ void gemm_kernel(const float* __restrict__ X, const float* __restrict__ W,
                            float* __restrict__ C, int nrows) {
    constexpr int CG = FOUT / 4;
    constexpr int TM = 128;
    constexpr int XPITCH = TK + 4;
    extern __shared__ float smem[];
    float* Xs = smem;                   // TM * XPITCH
    float* Ws = smem + TM * XPITCH;     // TK * FOUT

    const int tid = threadIdx.x;
    const int cg = tid % CG;
    const int rg = tid / CG;
    const int rowBase = blockIdx.x * TM;

    unsigned long long acc01[8], acc23[8];
#pragma unroll
    for (int i = 0; i < 8; i++) { acc01[i] = 0ull; acc23[i] = 0ull; }

    for (int k0 = 0; k0 < FIN; k0 += TK) {
        __syncthreads();
        for (int idx = tid; idx < TM * (TK / 4); idx += blockDim.x) {
            int r = idx / (TK / 4);
            int k4 = idx % (TK / 4);
            float4 v = make_float4(0.f, 0.f, 0.f, 0.f);
            int row = rowBase + r;
            if (row < nrows)
                v = *(const float4*)(X + (size_t)row * FIN + k0 + k4 * 4);
            *(float4*)(Xs + r * XPITCH + k4 * 4) = v;
        }
        for (int idx = tid; idx < TK * CG; idx += blockDim.x) {
            int k = idx / CG;
            int c4 = idx % CG;
            *(float4*)(Ws + k * FOUT + c4 * 4) =
                *(const float4*)(W + (size_t)(k0 + k) * FOUT + c4 * 4);
        }
        __syncthreads();

#pragma unroll 4
        for (int k = 0; k < TK; k++) {
            ulonglong2 wv = *(const ulonglong2*)(Ws + k * FOUT + cg * 4);
#pragma unroll
            for (int i = 0; i < 8; i++) {
                unsigned long long x2 = bcast2(Xs[(rg * 8 + i) * XPITCH + k]);
                ffma2(acc01[i], x2, wv.x);
                ffma2(acc23[i], x2, wv.y);
            }
        }
    }

#pragma unroll
    for (int i = 0; i < 8; i++) {
        int row = rowBase + rg * 8 + i;
        if (row < nrows) {
            float2 lo = unpack2(acc01[i]);
            float2 hi = unpack2(acc23[i]);
            float4 v = make_float4(lo.x, lo.y, hi.x, hi.y);
            *(float4*)(C + (size_t)row * FOUT + cg * 4) = v;
        }
    }
}

// ---------------- CSR construction ----------------
__global__ void hist_kernel(const int* __restrict__ dsts) {
    int e = blockIdx.x * blockDim.x + threadIdx.x;
    if (e >= ETOT) return;
    int d = (e < EE) ? __ldg(dsts + e) : (e - EE);
    atomicAdd(&g_deg[d], 1);
}

__global__ void scan_kernel() {
    __shared__ int sums[1024];
    const int t = threadIdx.x;
    constexpr int CH = (NN + 1 + 1023) / 1024;  // 49
    const int base = t * CH;
    int s = 0;
    for (int j = 0; j < CH; j++) {
        int idx = base + j;
        if (idx < NN) s += g_deg[idx];
    }
    sums[t] = s;
    __syncthreads();
    for (int off = 1; off < 1024; off <<= 1) {
        int v = (t >= off) ? sums[t - off] : 0;
        __syncthreads();
        sums[t] += v;
        __syncthreads();
    }
    int run = (t == 0) ? 0 : sums[t - 1];
    for (int j = 0; j < CH; j++) {
        int idx = base + j;
        if (idx <= NN) {
            g_rowptr[idx] = run;
            if (idx < NN) {
                g_cursor[idx] = run;
                run += g_deg[idx];
            }
        }
    }
}

__global__ void fill_kernel(const int* __restrict__ srcs, const int* __restrict__ dsts) {
    int e = blockIdx.x * blockDim.x + threadIdx.x;
    if (e >= ETOT) return;
    int s, d;
    if (e < EE) { s = __ldg(srcs + e); d = __ldg(dsts + e); }
    else        { s = d = e - EE; }
    int pos = atomicAdd(&g_cursor[d], 1);
    g_csr[pos] = s;
}

// ---------------- prep: attention logits ----------------
template <int H, int C>
__global__ void prep_kernel(const float* __restrict__ h,
                            const float* __restrict__ a_src,
                            const float* __restrict__ a_dst) {
    int t = blockIdx.x * blockDim.x + threadIdx.x;
    if (t >= NN * H) return;
    int n = t / H, hh = t % H;
    const float* hp = h + (size_t)n * (H * C) + hh * C;
    const float* sv = a_src + hh * C;
    const float* dv = a_dst + hh * C;
    float s1 = 0.f, s2 = 0.f;
#pragma unroll
    for (int c = 0; c < C; c++) {
        float v = hp[c];
        s1 += v * sv[c];
        s2 += v * dv[c];
    }
    g_as[t] = s1;
    g_ad[t] = s2;
}

// ---------------- aggregate: gather-side softmax-weighted sum + bias (+relu) ----------------
// 16 lanes per destination node; lane q owns feature float4 q (head = q/4 for H=4).
template <int H, int C, bool RELU>
__global__ void aggregate_kernel(const float* __restrict__ h,
                                 const float* __restrict__ bias,
                                 float* __restrict__ dest) {
    constexpr int F = H * C;
    constexpr int NV = F / 4;   // 16 or 10
    int gt = blockIdx.x * blockDim.x + threadIdx.x;
    int n = gt >> 4;
    int q = gt & 15;
    if (n >= NN) return;
    int hh = (H == 1) ? 0 : (q >> 2);

    const float ad = g_ad[n * H + hh];
    const int beg = __ldg(g_rowptr + n);
    const int end = __ldg(g_rowptr + n + 1);

    float4 acc = make_float4(0.f, 0.f, 0.f, 0.f);
    float den = 0.f;
    for (int i = beg; i < end; i++) {
        int s = __ldg(g_csr + i);
        float v = __ldg(g_as + s * H + hh) + ad;
        v = v > 0.f ? v : 0.2f * v;
        float w = __expf(v);
        den += w;
        if (q < NV) {
            float4 x = __ldg((const float4*)(h + (size_t)s * F) + q);
            acc.x += w * x.x;
            acc.y += w * x.y;
            acc.z += w * x.z;
            acc.w += w * x.w;
        }
    }
    if (q < NV) {
        float inv = 1.f / (den + 1e-16f);
        float4 b = __ldg((const float4*)bias + q);
        float4 o;
        o.x = acc.x * inv + b.x;
        o.y = acc.y * inv + b.y;
        o.z = acc.z * inv + b.z;
        o.w = acc.w * inv + b.w;
        if (RELU) {
            o.x = o.x > 0.f ? o.x : 0.f;
            o.y = o.y > 0.f ? o.y : 0.f;
            o.z = o.z > 0.f ? o.z : 0.f;
            o.w = o.w > 0.f ? o.w : 0.f;
        }
        *(float4*)(dest + (size_t)n * F + q * 4) = o;
    }
}

// ---------------- launch ----------------
extern "C" void kernel_launch(void* const* d_in, const int* in_sizes, int n_in,
                              void* d_out, int out_size) {
    const float* x = (const float*)d_in[0];
    const int* ei = (const int*)d_in[1];    // int32 (JAX x64 disabled)
    const float* W1 = (const float*)d_in[2];
    const float* asr1 = (const float*)d_in[3];
    const float* adr1 = (const float*)d_in[4];
    const float* b1 = (const float*)d_in[5];
    const float* W2 = (const float*)d_in[6];
    const float* asr2 = (const float*)d_in[7];
    const float* adr2 = (const float*)d_in[8];
    const float* b2 = (const float*)d_in[9];
    const float* W3 = (const float*)d_in[10];
    const float* asr3 = (const float*)d_in[11];
    const float* adr3 = (const float*)d_in[12];
    const float* b3 = (const float*)d_in[13];
    float* out = (float*)d_out;

    const int* esrc = ei;
    const int* edst = ei + EE;

    float *p_h, *p_feat;
    void* p_deg;
    cudaGetSymbolAddress((void**)&p_h, g_h);
    cudaGetSymbolAddress((void**)&p_feat, g_feat);
    cudaGetSymbolAddress(&p_deg, g_deg);

    constexpr int SMEM1 = (128 * (64 + 4) + 64 * 64) * 4;
    constexpr int SMEM3 = (128 * (64 + 4) + 64 * 40) * 4;
    cudaFuncSetAttribute((const void*)gemm_kernel<256, 64, 64>,
                         cudaFuncAttributeMaxDynamicSharedMemorySize, SMEM1);
    cudaFuncSetAttribute((const void*)gemm_kernel<64, 64, 64>,
                         cudaFuncAttributeMaxDynamicSharedMemorySize, SMEM1);
    cudaFuncSetAttribute((const void*)gemm_kernel<64, 40, 64>,
                         cudaFuncAttributeMaxDynamicSharedMemorySize, SMEM3);

    const int gemmGrid = (NN + 127) / 128;
    const int edgeGrid = (ETOT + 255) / 256;
    const int aggGrid = (NN * 16 + 255) / 256;

    // ---------------- CSR build (shared by all 3 layers) ----------------
    cudaMemsetAsync(p_deg, 0, NN * sizeof(int));
    hist_kernel<<<edgeGrid, 256>>>(edst);
    scan_kernel<<<1, 1024>>>();
    fill_kernel<<<edgeGrid, 256>>>(esrc, edst);

    // ---------------- layer 1: 256 -> 4x16 ----------------
    gemm_kernel<256, 64, 64><<<gemmGrid, 256, SMEM1>>>(x, W1, p_h, NN);
    prep_kernel<4, 16><<<(NN * 4 + 255) / 256, 256>>>(p_h, asr1, adr1);
    aggregate_kernel<4, 16, true><<<aggGrid, 256>>>(p_h, b1, p_feat);

    // ---------------- layer 2: 64 -> 4x16 ----------------
    gemm_kernel<64, 64, 64><<<gemmGrid, 256, SMEM1>>>(p_feat, W2, p_h, NN);
    prep_kernel<4, 16><<<(NN * 4 + 255) / 256, 256>>>(p_h, asr2, adr2);
    aggregate_kernel<4, 16, true><<<aggGrid, 256>>>(p_h, b2, p_feat);

    // ---------------- layer 3: 64 -> 1x40 ----------------
    gemm_kernel<64, 40, 64><<<gemmGrid, 160, SMEM3>>>(p_feat, W3, p_h, NN);
    prep_kernel<1, 40><<<(NN + 255) / 256, 256>>>(p_h, asr3, adr3);
    aggregate_kernel<1, 40, false><<<aggGrid, 256>>>(p_h, b3, out);
}

// round 6
// speedup vs baseline: 2.1100x; 1.0522x over previous
#include <cuda_runtime.h>
#include <math.h>
#include <stdint.h>

#define NN 50000
#define EE 800000
#define ETOT (EE + NN)

// ---------------- device scratch ----------------
__device__ __align__(16) float g_h[NN * 64];     // pre-attention features
__device__ __align__(16) float g_feat[NN * 64];  // layer output -> next input
__device__ __align__(16) float g_as[NN * 4];     // alpha_src per (node, head)
__device__ __align__(16) float g_ad[NN * 4];     // alpha_dst per (node, head)
__device__ int g_deg[NN];         // in-degree histogram
__device__ int g_rowptr[NN + 1];  // CSR row pointers
__device__ int g_cursor[NN];      // fill cursors
__device__ int g_csr[ETOT];       // CSR src indices (incl. self loops)

// ---------------- packed f32x2 helpers ----------------
__device__ __forceinline__ void ffma2(unsigned long long& acc, unsigned long long a,
                                      unsigned long long b) {
    asm("fma.rn.f32x2 %0, %1, %2, %0;" : "+l"(acc) : "l"(a), "l"(b));
}
__device__ __forceinline__ unsigned long long bcast2(float x) {
    unsigned long long r;
    asm("mov.b64 %0, {%1, %1};" : "=l"(r) : "f"(x));
    return r;
}
__device__ __forceinline__ float2 unpack2(unsigned long long p) {
    float2 f;
    asm("mov.b64 {%0, %1}, %2;" : "=f"(f.x), "=f"(f.y) : "l"(p));
    return f;
}

// ---------------- GEMM: C[n, FOUT] = X[n, FIN] * W[FIN, FOUT] ----------------
// TM=64 rows/block, 4 rows x 4 cols per thread, f32x2 FMA.
// If ALPHA: fused attention-logit epilogue (requires FOUT=64, H=4, C=16, CG=16).
template <int FIN, int FOUT, int TK, bool ALPHA>
__global__ void __launch_bounds__(FOUT * 4, 1) gemm_kernel(
    const float* __restrict__ X, const float* __restrict__ W,
    float* __restrict__ C, const float* __restrict__ asrc,
    const float* __restrict__ adst, int nrows) {
    constexpr int CG = FOUT / 4;
    constexpr int TM = 64;
    constexpr int XPITCH = TK + 4;
    extern __shared__ float smem[];
    float* Xs = smem;                   // TM * XPITCH
    float* Ws = smem + TM * XPITCH;     // TK * FOUT

    const int tid = threadIdx.x;
    const int cg = tid % CG;
    const int rg = tid / CG;            // 0..15
    const int rowBase = blockIdx.x * TM;

    float a_s[4], a_d[4];
    if (ALPHA) {
#pragma unroll
        for (int j = 0; j < 4; j++) {
            a_s[j] = __ldg(asrc + cg * 4 + j);
            a_d[j] = __ldg(adst + cg * 4 + j);
        }
    }

    unsigned long long acc01[4], acc23[4];
#pragma unroll
    for (int i = 0; i < 4; i++) { acc01[i] = 0ull; acc23[i] = 0ull; }

    for (int k0 = 0; k0 < FIN; k0 += TK) {
        __syncthreads();
        for (int idx = tid; idx < TM * (TK / 4); idx += blockDim.x) {
            int r = idx / (TK / 4);
            int k4 = idx % (TK / 4);
            float4 v = make_float4(0.f, 0.f, 0.f, 0.f);
            int row = rowBase + r;
            if (row < nrows)
                v = *(const float4*)(X + (size_t)row * FIN + k0 + k4 * 4);
            *(float4*)(Xs + r * XPITCH + k4 * 4) = v;
        }
        for (int idx = tid; idx < TK * CG; idx += blockDim.x) {
            int k = idx / CG;
            int c4 = idx % CG;
            *(float4*)(Ws + k * FOUT + c4 * 4) =
                *(const float4*)(W + (size_t)(k0 + k) * FOUT + c4 * 4);
        }
        __syncthreads();

#pragma unroll 2
        for (int k4 = 0; k4 < TK / 4; k4++) {
            float4 xq[4];
#pragma unroll
            for (int i = 0; i < 4; i++)
                xq[i] = *(float4*)(Xs + (rg * 4 + i) * XPITCH + k4 * 4);
#pragma unroll
            for (int kk = 0; kk < 4; kk++) {
                ulonglong2 wv = *(const ulonglong2*)(Ws + (k4 * 4 + kk) * FOUT + cg * 4);
#pragma unroll
                for (int i = 0; i < 4; i++) {
                    float xv = (kk == 0) ? xq[i].x : (kk == 1) ? xq[i].y
                              : (kk == 2) ? xq[i].z : xq[i].w;
                    unsigned long long x2 = bcast2(xv);
                    ffma2(acc01[i], x2, wv.x);
                    ffma2(acc23[i], x2, wv.y);
                }
            }
        }
    }

#pragma unroll
    for (int i = 0; i < 4; i++) {
        int row = rowBase + rg * 4 + i;
        float2 lo = unpack2(acc01[i]);
        float2 hi = unpack2(acc23[i]);
        float4 v = make_float4(lo.x, lo.y, hi.x, hi.y);
        if (row < nrows)
            *(float4*)(C + (size_t)row * FOUT + cg * 4) = v;
        if (ALPHA) {
            // per-thread partial dot over this thread's 4 cols (all in head cg>>2)
            float p1 = v.x * a_s[0] + v.y * a_s[1] + v.z * a_s[2] + v.w * a_s[3];
            float p2 = v.x * a_d[0] + v.y * a_d[1] + v.z * a_d[2] + v.w * a_d[3];
            p1 += __shfl_xor_sync(0xffffffffu, p1, 1);
            p1 += __shfl_xor_sync(0xffffffffu, p1, 2);
            p2 += __shfl_xor_sync(0xffffffffu, p2, 1);
            p2 += __shfl_xor_sync(0xffffffffu, p2, 2);
            if ((cg & 3) == 0 && row < nrows) {
                g_as[row * 4 + (cg >> 2)] = p1;
                g_ad[row * 4 + (cg >> 2)] = p2;
            }
        }
    }
}

// ---------------- CSR construction ----------------
__global__ void hist_kernel(const int* __restrict__ dsts) {
    int e = blockIdx.x * blockDim.x + threadIdx.x;
    if (e >= ETOT) return;
    int d = (e < EE) ? __ldg(dsts + e) : (e - EE);
    atomicAdd(&g_deg[d], 1);
}

__global__ void scan_kernel() {
    __shared__ int sums[1024];
    const int t = threadIdx.x;
    constexpr int CH = (NN + 1 + 1023) / 1024;
    const int base = t * CH;
    int s = 0;
    for (int j = 0; j < CH; j++) {
        int idx = base + j;
        if (idx < NN) s += g_deg[idx];
    }
    sums[t] = s;
    __syncthreads();
    for (int off = 1; off < 1024; off <<= 1) {
        int v = (t >= off) ? sums[t - off] : 0;
        __syncthreads();
        sums[t] += v;
        __syncthreads();
    }
    int run = (t == 0) ? 0 : sums[t - 1];
    for (int j = 0; j < CH; j++) {
        int idx = base + j;
        if (idx <= NN) {
            g_rowptr[idx] = run;
            if (idx < NN) {
                g_cursor[idx] = run;
                run += g_deg[idx];
            }
        }
    }
}

__global__ void fill_kernel(const int* __restrict__ srcs, const int* __restrict__ dsts) {
    int e = blockIdx.x * blockDim.x + threadIdx.x;
    if (e >= ETOT) return;
    int s, d;
    if (e < EE) { s = __ldg(srcs + e); d = __ldg(dsts + e); }
    else        { s = d = e - EE; }
    int pos = atomicAdd(&g_cursor[d], 1);
    g_csr[pos] = s;
}

// ---------------- prep (layer 3 only): attention logits ----------------
template <int H, int C>
__global__ void prep_kernel(const float* __restrict__ h,
                            const float* __restrict__ a_src,
                            const float* __restrict__ a_dst) {
    int t = blockIdx.x * blockDim.x + threadIdx.x;
    if (t >= NN * H) return;
    int n = t / H, hh = t % H;
    const float* hp = h + (size_t)n * (H * C) + hh * C;
    const float* sv = a_src + hh * C;
    const float* dv = a_dst + hh * C;
    float s1 = 0.f, s2 = 0.f;
#pragma unroll
    for (int c = 0; c < C; c++) {
        float v = hp[c];
        s1 += v * sv[c];
        s2 += v * dv[c];
    }
    g_as[t] = s1;
    g_ad[t] = s2;
}

// ---------------- aggregate: gather-side softmax-weighted sum + bias (+relu) ----------------
template <int H, int C, bool RELU>
__global__ void aggregate_kernel(const float* __restrict__ h,
                                 const float* __restrict__ bias,
                                 float* __restrict__ dest) {
    constexpr int F = H * C;
    constexpr int NV = F / 4;
    int gt = blockIdx.x * blockDim.x + threadIdx.x;
    int n = gt >> 4;
    int q = gt & 15;
    if (n >= NN) return;
    int hh = (H == 1) ? 0 : (q >> 2);

    const float ad = g_ad[n * H + hh];
    const int beg = __ldg(g_rowptr + n);
    const int end = __ldg(g_rowptr + n + 1);

    float4 acc = make_float4(0.f, 0.f, 0.f, 0.f);
    float den = 0.f;
    for (int i = beg; i < end; i++) {
        int s = __ldg(g_csr + i);
        float v = __ldg(g_as + s * H + hh) + ad;
        v = v > 0.f ? v : 0.2f * v;
        float w = __expf(v);
        den += w;
        if (q < NV) {
            float4 x = __ldg((const float4*)(h + (size_t)s * F) + q);
            acc.x += w * x.x;
            acc.y += w * x.y;
            acc.z += w * x.z;
            acc.w += w * x.w;
        }
    }
    if (q < NV) {
        float inv = 1.f / (den + 1e-16f);
        float4 b = __ldg((const float4*)bias + q);
        float4 o;
        o.x = acc.x * inv + b.x;
        o.y = acc.y * inv + b.y;
        o.z = acc.z * inv + b.z;
        o.w = acc.w * inv + b.w;
        if (RELU) {
            o.x = o.x > 0.f ? o.x : 0.f;
            o.y = o.y > 0.f ? o.y : 0.f;
            o.z = o.z > 0.f ? o.z : 0.f;
            o.w = o.w > 0.f ? o.w : 0.f;
        }
        *(float4*)(dest + (size_t)n * F + q * 4) = o;
    }
}

// ---------------- launch ----------------
extern "C" void kernel_launch(void* const* d_in, const int* in_sizes, int n_in,
                              void* d_out, int out_size) {
    const float* x = (const float*)d_in[0];
    const int* ei = (const int*)d_in[1];    // int32 (JAX x64 disabled)
    const float* W1 = (const float*)d_in[2];
    const float* asr1 = (const float*)d_in[3];
    const float* adr1 = (const float*)d_in[4];
    const float* b1 = (const float*)d_in[5];
    const float* W2 = (const float*)d_in[6];
    const float* asr2 = (const float*)d_in[7];
    const float* adr2 = (const float*)d_in[8];
    const float* b2 = (const float*)d_in[9];
    const float* W3 = (const float*)d_in[10];
    const float* asr3 = (const float*)d_in[11];
    const float* adr3 = (const float*)d_in[12];
    const float* b3 = (const float*)d_in[13];
    float* out = (float*)d_out;

    const int* esrc = ei;
    const int* edst = ei + EE;

    float *p_h, *p_feat;
    void* p_deg;
    cudaGetSymbolAddress((void**)&p_h, g_h);
    cudaGetSymbolAddress((void**)&p_feat, g_feat);
    cudaGetSymbolAddress(&p_deg, g_deg);

    constexpr int SMEM64 = (64 * (64 + 4) + 64 * 64) * 4;  // 33792
    constexpr int SMEM40 = (64 * (64 + 4) + 64 * 40) * 4;  // 27648

    const int gemmGrid = (NN + 63) / 64;   // 782
    const int edgeGrid = (ETOT + 255) / 256;
    const int aggGrid = (NN * 16 + 255) / 256;

    // ---------------- CSR build (shared by all 3 layers) ----------------
    cudaMemsetAsync(p_deg, 0, NN * sizeof(int));
    hist_kernel<<<edgeGrid, 256>>>(edst);
    scan_kernel<<<1, 1024>>>();
    fill_kernel<<<edgeGrid, 256>>>(esrc, edst);

    // ---------------- layer 1: 256 -> 4x16 ----------------
    gemm_kernel<256, 64, 64, true><<<gemmGrid, 256, SMEM64>>>(x, W1, p_h, asr1, adr1, NN);
    aggregate_kernel<4, 16, true><<<aggGrid, 256>>>(p_h, b1, p_feat);

    // ---------------- layer 2: 64 -> 4x16 ----------------
    gemm_kernel<64, 64, 64, true><<<gemmGrid, 256, SMEM64>>>(p_feat, W2, p_h, asr2, adr2, NN);
    aggregate_kernel<4, 16, true><<<aggGrid, 256>>>(p_h, b2, p_feat);

    // ---------------- layer 3: 64 -> 1x40 ----------------
    gemm_kernel<64, 40, 64, false><<<gemmGrid, 160, SMEM40>>>(p_feat, W3, p_h, nullptr, nullptr, NN);
    prep_kernel<1, 40><<<(NN + 255) / 256, 256>>>(p_h, asr3, adr3);
    aggregate_kernel<1, 40, false><<<aggGrid, 256>>>(p_h, b3, out);
}